// round 2
// baseline (speedup 1.0000x reference)
#include <cuda_runtime.h>
#include <cstdint>

namespace {

constexpr int ATOM = 128;   // atom feature dim (first part of concat)
constexpr int BOND = 64;    // bond feature dim (second part of concat)
constexpr int KTOT = 192;   // ATOM + BOND
constexpr int NOUT = 256;   // message dim
constexpr int BM   = 64;    // edges per CTA
constexpr int BK   = 32;    // K chunk
constexpr int NTHREADS = 256;
constexpr int SSTRIDE  = 36; // padded smem row stride (words) -> conflict-free

__device__ __forceinline__ uint32_t f2tf32(float x) {
    uint32_t r;
    asm("cvt.rna.tf32.f32 %0, %1;" : "=r"(r) : "f"(x));
    return r;
}

__global__ void __launch_bounds__(NTHREADS, 2)
bond_msg_kernel(const float* __restrict__ V,
                const float* __restrict__ E,
                const int* __restrict__ src_idx,         // edge_index row 0 (int32!)
                const float* __restrict__ W,             // [NOUT, KTOT]
                const float* __restrict__ bias,          // [NOUT]
                float* __restrict__ out,                 // [M, NOUT]
                int M)
{
    __shared__ uint32_t As[BM][SSTRIDE];     // gathered+concat A tile (tf32 bits)
    __shared__ uint32_t Bs[NOUT][SSTRIDE];   // W tile (tf32 bits), row = out col
    __shared__ int      srcs[BM];

    const int tid  = threadIdx.x;
    const int lane = tid & 31;
    const int wid  = tid >> 5;
    const int warp_m = wid >> 2;   // 0..1  (32 rows each)
    const int warp_n = wid & 3;    // 0..3  (64 cols each)
    const int lr = lane >> 2;      // 0..7  (groupID)
    const int lc = lane & 3;       // 0..3  (threadID in group)

    const int e0 = blockIdx.x * BM;

    if (tid < BM) {
        int e = e0 + tid;
        if (e >= M) e = M - 1;
        srcs[tid] = src_idx[e];                // int32 read — JAX canonicalized int64->int32
    }
    __syncthreads();

    float acc[2][8][4];
    #pragma unroll
    for (int mi = 0; mi < 2; ++mi)
        #pragma unroll
        for (int ni = 0; ni < 8; ++ni)
            #pragma unroll
            for (int c = 0; c < 4; ++c)
                acc[mi][ni][c] = 0.f;

    #pragma unroll
    for (int ck = 0; ck < KTOT / BK; ++ck) {
        const int k0 = ck * BK;

        // ---- A tile: 64 rows x 32 cols = 512 float4, 2 per thread.
        // Gathered from V (k0 < 128) or E (k0 >= 128); chunk never straddles.
        #pragma unroll
        for (int i = 0; i < 2; ++i) {
            int idx = tid + i * NTHREADS;        // 0..511
            int r   = idx >> 3;
            int f4  = idx & 7;
            int er  = e0 + r; if (er >= M) er = M - 1;
            const float* p = (k0 < ATOM)
                ? (V + (size_t)srcs[r] * ATOM + (k0 + f4 * 4))
                : (E + (size_t)er * BOND + (k0 - ATOM + f4 * 4));
            float4 v = *(const float4*)p;
            uint32_t* d = &As[r][f4 * 4];
            d[0] = f2tf32(v.x); d[1] = f2tf32(v.y);
            d[2] = f2tf32(v.z); d[3] = f2tf32(v.w);
        }

        // ---- B tile: 256 rows x 32 cols = 2048 float4, 8 per thread.
        #pragma unroll
        for (int i = 0; i < 8; ++i) {
            int idx = tid + i * NTHREADS;        // 0..2047
            int r   = idx >> 3;
            int f4  = idx & 7;
            float4 v = *(const float4*)(W + (size_t)r * KTOT + k0 + f4 * 4);
            uint32_t* d = &Bs[r][f4 * 4];
            d[0] = f2tf32(v.x); d[1] = f2tf32(v.y);
            d[2] = f2tf32(v.z); d[3] = f2tf32(v.w);
        }
        __syncthreads();

        // ---- 4 k8-steps of m16n8k8 tf32 mma; warp tile 32x64 -> 2x8 mmas.
        #pragma unroll
        for (int kk = 0; kk < 4; ++kk) {
            const int kb = kk * 8;
            uint32_t a[2][4], b[8][2];
            #pragma unroll
            for (int mi = 0; mi < 2; ++mi) {
                int r = warp_m * 32 + mi * 16 + lr;
                a[mi][0] = As[r    ][kb + lc];
                a[mi][1] = As[r + 8][kb + lc];
                a[mi][2] = As[r    ][kb + lc + 4];
                a[mi][3] = As[r + 8][kb + lc + 4];
            }
            #pragma unroll
            for (int ni = 0; ni < 8; ++ni) {
                int n = warp_n * 64 + ni * 8 + lr;
                b[ni][0] = Bs[n][kb + lc];
                b[ni][1] = Bs[n][kb + lc + 4];
            }
            #pragma unroll
            for (int mi = 0; mi < 2; ++mi)
                #pragma unroll
                for (int ni = 0; ni < 8; ++ni) {
                    asm volatile(
                        "mma.sync.aligned.m16n8k8.row.col.f32.tf32.tf32.f32 "
                        "{%0,%1,%2,%3}, {%4,%5,%6,%7}, {%8,%9}, {%0,%1,%2,%3};\n"
                        : "+f"(acc[mi][ni][0]), "+f"(acc[mi][ni][1]),
                          "+f"(acc[mi][ni][2]), "+f"(acc[mi][ni][3])
                        : "r"(a[mi][0]), "r"(a[mi][1]),
                          "r"(a[mi][2]), "r"(a[mi][3]),
                          "r"(b[ni][0]), "r"(b[ni][1]));
                }
        }
        __syncthreads();
    }

    // ---- Epilogue: add bias, store. c0/c1 -> (row, 2lc..2lc+1), c2/c3 -> row+8.
    #pragma unroll
    for (int mi = 0; mi < 2; ++mi) {
        int row0 = e0 + warp_m * 32 + mi * 16 + lr;
        int row1 = row0 + 8;
        #pragma unroll
        for (int ni = 0; ni < 8; ++ni) {
            int col = warp_n * 64 + ni * 8 + 2 * lc;
            float2 bb = *(const float2*)(bias + col);
            if (row0 < M) {
                float2 o;
                o.x = acc[mi][ni][0] + bb.x;
                o.y = acc[mi][ni][1] + bb.y;
                *(float2*)(out + (size_t)row0 * NOUT + col) = o;
            }
            if (row1 < M) {
                float2 o;
                o.x = acc[mi][ni][2] + bb.x;
                o.y = acc[mi][ni][3] + bb.y;
                *(float2*)(out + (size_t)row1 * NOUT + col) = o;
            }
        }
    }
}

} // namespace

extern "C" void kernel_launch(void* const* d_in, const int* in_sizes, int n_in,
                              void* d_out, int out_size)
{
    const float* V   = (const float*)d_in[0];
    const float* E   = (const float*)d_in[1];
    const int*   EI  = (const int*)d_in[2];   // int32 [2, M]; row 0 = src
    const float* W   = (const float*)d_in[3];
    const float* b   = (const float*)d_in[4];
    float*       out = (float*)d_out;

    const int M = in_sizes[1] / BOND;   // n_edges from E element count
    const int grid = (M + BM - 1) / BM;

    bond_msg_kernel<<<grid, NTHREADS>>>(V, E, EI, W, b, out, M);
}

// round 4
// speedup vs baseline: 1.3059x; 1.3059x over previous
#include <cuda_runtime.h>
#include <cuda_fp16.h>
#include <cstdint>

namespace {

constexpr int ATOM = 128;   // atom feature dim (first part of concat)
constexpr int BOND = 64;    // bond feature dim (second part of concat)
constexpr int KTOT = 192;   // ATOM + BOND
constexpr int NOUT = 256;   // message dim
constexpr int BM   = 64;    // edges per CTA
constexpr int BKF  = 32;    // K chunk in floats
constexpr int BKW  = 16;    // K chunk in half2 words
constexpr int NTHREADS = 256;
constexpr int SSTRIDE  = 20; // padded smem row stride (words): (20*lr+lc)%32 all-distinct

__device__ __forceinline__ uint32_t h2(float lo, float hi) {
    __half2 h = __floats2half2_rn(lo, hi);
    return *(uint32_t*)&h;
}

__global__ void __launch_bounds__(NTHREADS, 2)
bond_msg_kernel(const float* __restrict__ V,
                const float* __restrict__ E,
                const int* __restrict__ src_idx,         // edge_index row 0 (int32)
                const float* __restrict__ W,             // [NOUT, KTOT]
                const float* __restrict__ bias,          // [NOUT]
                float* __restrict__ out,                 // [M, NOUT]
                int M)
{
    __shared__ uint32_t As[BM][SSTRIDE];     // gathered+concat A tile (half2 words)
    __shared__ uint32_t Bs[NOUT][SSTRIDE];   // W tile (half2 words), row = out col
    __shared__ int      srcs[BM];

    const int tid  = threadIdx.x;
    const int lane = tid & 31;
    const int wid  = tid >> 5;
    const int warp_m = wid >> 2;   // 0..1  (32 rows each)
    const int warp_n = wid & 3;    // 0..3  (64 cols each)
    const int lr = lane >> 2;      // 0..7  groupID
    const int lc = lane & 3;       // 0..3  threadID-in-group

    const int e0 = blockIdx.x * BM;

    if (tid < BM) {
        int e = e0 + tid;
        if (e >= M) e = M - 1;
        srcs[tid] = src_idx[e];
    }
    __syncthreads();

    float acc[2][8][4];
    #pragma unroll
    for (int mi = 0; mi < 2; ++mi)
        #pragma unroll
        for (int ni = 0; ni < 8; ++ni)
            #pragma unroll
            for (int c = 0; c < 4; ++c)
                acc[mi][ni][c] = 0.f;

    #pragma unroll
    for (int ck = 0; ck < KTOT / BKF; ++ck) {
        const int k0 = ck * BKF;

        // ---- A tile: 64 rows x 32 float cols -> 512 float4, 2 per thread.
        // Gathered from V (k0 < 128) or E (k0 >= 128); chunk never straddles.
        #pragma unroll
        for (int i = 0; i < 2; ++i) {
            int idx = tid + i * NTHREADS;        // 0..511
            int r   = idx >> 3;
            int f4  = idx & 7;
            int er  = e0 + r; if (er >= M) er = M - 1;
            const float* p = (k0 < ATOM)
                ? (V + (size_t)srcs[r] * ATOM + (k0 + f4 * 4))
                : (E + (size_t)er * BOND + (k0 - ATOM + f4 * 4));
            float4 v = *(const float4*)p;
            As[r][f4 * 2]     = h2(v.x, v.y);
            As[r][f4 * 2 + 1] = h2(v.z, v.w);
        }

        // ---- B tile: 256 rows x 32 float cols -> 2048 float4, 8 per thread.
        #pragma unroll
        for (int i = 0; i < 8; ++i) {
            int idx = tid + i * NTHREADS;        // 0..2047
            int n   = idx >> 3;
            int f4  = idx & 7;
            float4 v = *(const float4*)(W + (size_t)n * KTOT + k0 + f4 * 4);
            Bs[n][f4 * 2]     = h2(v.x, v.y);
            Bs[n][f4 * 2 + 1] = h2(v.z, v.w);
        }
        __syncthreads();

        // ---- 2 k16-steps of m16n8k16 f16 mma; warp tile 32x64 -> 2x8 mmas.
        // Word-space fragment indices identical to the tf32 m16n8k8 kernel.
        #pragma unroll
        for (int kk = 0; kk < 2; ++kk) {
            const int kb = kk * 8;
            uint32_t a[2][4], b[8][2];
            #pragma unroll
            for (int mi = 0; mi < 2; ++mi) {
                int r = warp_m * 32 + mi * 16 + lr;
                a[mi][0] = As[r    ][kb + lc];
                a[mi][1] = As[r + 8][kb + lc];
                a[mi][2] = As[r    ][kb + lc + 4];
                a[mi][3] = As[r + 8][kb + lc + 4];
            }
            #pragma unroll
            for (int ni = 0; ni < 8; ++ni) {
                int n = warp_n * 64 + ni * 8 + lr;
                b[ni][0] = Bs[n][kb + lc];
                b[ni][1] = Bs[n][kb + lc + 4];
            }
            #pragma unroll
            for (int mi = 0; mi < 2; ++mi)
                #pragma unroll
                for (int ni = 0; ni < 8; ++ni) {
                    asm volatile(
                        "mma.sync.aligned.m16n8k16.row.col.f32.f16.f16.f32 "
                        "{%0,%1,%2,%3}, {%4,%5,%6,%7}, {%8,%9}, {%0,%1,%2,%3};\n"
                        : "+f"(acc[mi][ni][0]), "+f"(acc[mi][ni][1]),
                          "+f"(acc[mi][ni][2]), "+f"(acc[mi][ni][3])
                        : "r"(a[mi][0]), "r"(a[mi][1]),
                          "r"(a[mi][2]), "r"(a[mi][3]),
                          "r"(b[ni][0]), "r"(b[ni][1]));
                }
        }
        __syncthreads();
    }

    // ---- Epilogue: add bias, store. c0/c1 -> (row, 2lc..2lc+1), c2/c3 -> row+8.
    #pragma unroll
    for (int mi = 0; mi < 2; ++mi) {
        int row0 = e0 + warp_m * 32 + mi * 16 + lr;
        int row1 = row0 + 8;
        #pragma unroll
        for (int ni = 0; ni < 8; ++ni) {
            int col = warp_n * 64 + ni * 8 + 2 * lc;
            float2 bb = *(const float2*)(bias + col);
            if (row0 < M) {
                float2 o;
                o.x = acc[mi][ni][0] + bb.x;
                o.y = acc[mi][ni][1] + bb.y;
                *(float2*)(out + (size_t)row0 * NOUT + col) = o;
            }
            if (row1 < M) {
                float2 o;
                o.x = acc[mi][ni][2] + bb.x;
                o.y = acc[mi][ni][3] + bb.y;
                *(float2*)(out + (size_t)row1 * NOUT + col) = o;
            }
        }
    }
}

} // namespace

extern "C" void kernel_launch(void* const* d_in, const int* in_sizes, int n_in,
                              void* d_out, int out_size)
{
    const float* V   = (const float*)d_in[0];
    const float* E   = (const float*)d_in[1];
    const int*   EI  = (const int*)d_in[2];   // int32 (JAX canonicalized), row 0 = src
    const float* W   = (const float*)d_in[3];
    const float* b   = (const float*)d_in[4];
    float*       out = (float*)d_out;

    const int M = in_sizes[1] / BOND;   // n_edges from E element count
    const int grid = (M + BM - 1) / BM;

    bond_msg_kernel<<<grid, NTHREADS>>>(V, E, EI, W, b, out, M);
}

// round 5
// speedup vs baseline: 1.3303x; 1.0187x over previous
#include <cuda_runtime.h>
#include <cuda_fp16.h>
#include <cstdint>

namespace {

constexpr int ATOM = 128;
constexpr int BOND = 64;
constexpr int KTOT = 192;   // 48 float4 per row
constexpr int NOUT = 256;
constexpr int BM   = 128;   // edges per CTA
constexpr int NTHREADS = 512;
constexpr int KW   = KTOT / 2;          // 96 half2 words per row
constexpr int STRIDE = 100;             // padded row stride (words): 100%32=4 -> frag LDS conflict-free

// dynamic smem layout (in 4B words)
constexpr int SM_A_W   = 0;                         // As: 128 x 100
constexpr int SM_B_W   = BM * STRIDE;               // Bs: 256 x 100
constexpr int SM_SRC_W = SM_B_W + NOUT * STRIDE;    // 128 ints
constexpr int SMEM_BYTES = (SM_SRC_W + BM) * 4;     // 154112 B

__device__ __forceinline__ uint32_t h2(float lo, float hi) {
    __half2 h = __floats2half2_rn(lo, hi);
    return *(uint32_t*)&h;
}

__global__ void __launch_bounds__(NTHREADS, 1)
bond_msg_kernel(const float* __restrict__ V,
                const float* __restrict__ E,
                const int* __restrict__ src_idx,   // edge_index row 0 (int32)
                const float* __restrict__ W,       // [NOUT, KTOT]
                const float* __restrict__ bias,    // [NOUT]
                float* __restrict__ out,           // [M, NOUT]
                int M)
{
    extern __shared__ uint32_t smem[];
    uint32_t* As = smem + SM_A_W;      // [128][STRIDE] half2 words
    uint32_t* Bs = smem + SM_B_W;      // [256][STRIDE] half2 words
    int*      srcs = (int*)(smem + SM_SRC_W);

    const int tid  = threadIdx.x;
    const int lane = tid & 31;
    const int wid  = tid >> 5;
    const int warp_m = wid >> 2;   // 0..3 (32 rows each)
    const int warp_n = wid & 3;    // 0..3 (64 cols each)
    const int lr = lane >> 2;      // 0..7
    const int lc = lane & 3;       // 0..3

    const int e0 = blockIdx.x * BM;

    if (tid < BM) {
        int e = e0 + tid;
        if (e >= M) e = M - 1;
        srcs[tid] = src_idx[e];
    }
    __syncthreads();

    // ---- Fill B once: 256 rows x 48 float4 = 12288 float4, 24 per thread.
    #pragma unroll
    for (int i = 0; i < 24; ++i) {
        int idx = tid + i * NTHREADS;      // 0..12287
        int n  = idx / 48;
        int c4 = idx % 48;
        float4 v = *(const float4*)(W + (size_t)n * KTOT + c4 * 4);
        uint32_t* d = Bs + n * STRIDE + c4 * 2;
        d[0] = h2(v.x, v.y);
        d[1] = h2(v.z, v.w);
    }

    // ---- Fill A once (gathered + concat): 128 rows x 48 float4, 12 per thread.
    #pragma unroll
    for (int i = 0; i < 12; ++i) {
        int idx = tid + i * NTHREADS;      // 0..6143
        int r  = idx / 48;
        int c4 = idx % 48;
        const float* p;
        if (c4 < 32) {                     // atom part from V[src]
            p = V + (size_t)srcs[r] * ATOM + c4 * 4;
        } else {                           // bond part from E[edge]
            int er = e0 + r; if (er >= M) er = M - 1;
            p = E + (size_t)er * BOND + (c4 - 32) * 4;
        }
        float4 v = *(const float4*)p;
        uint32_t* d = As + r * STRIDE + c4 * 2;
        d[0] = h2(v.x, v.y);
        d[1] = h2(v.z, v.w);
    }
    __syncthreads();

    // ---- 12 k16-steps, fully unrolled, no barriers. Warp tile 32x64.
    float acc[2][8][4];
    #pragma unroll
    for (int mi = 0; mi < 2; ++mi)
        #pragma unroll
        for (int ni = 0; ni < 8; ++ni)
            #pragma unroll
            for (int c = 0; c < 4; ++c)
                acc[mi][ni][c] = 0.f;

    #pragma unroll
    for (int kk = 0; kk < 12; ++kk) {
        const int kb = kk * 8;
        uint32_t a[2][4], b[8][2];
        #pragma unroll
        for (int mi = 0; mi < 2; ++mi) {
            int r = warp_m * 32 + mi * 16 + lr;
            const uint32_t* ap = As + r * STRIDE + kb;
            a[mi][0] = ap[lc];
            a[mi][1] = ap[8 * STRIDE + lc];
            a[mi][2] = ap[lc + 4];
            a[mi][3] = ap[8 * STRIDE + lc + 4];
        }
        #pragma unroll
        for (int ni = 0; ni < 8; ++ni) {
            int n = warp_n * 64 + ni * 8 + lr;
            const uint32_t* bp = Bs + n * STRIDE + kb;
            b[ni][0] = bp[lc];
            b[ni][1] = bp[lc + 4];
        }
        #pragma unroll
        for (int mi = 0; mi < 2; ++mi)
            #pragma unroll
            for (int ni = 0; ni < 8; ++ni) {
                asm volatile(
                    "mma.sync.aligned.m16n8k16.row.col.f32.f16.f16.f32 "
                    "{%0,%1,%2,%3}, {%4,%5,%6,%7}, {%8,%9}, {%0,%1,%2,%3};\n"
                    : "+f"(acc[mi][ni][0]), "+f"(acc[mi][ni][1]),
                      "+f"(acc[mi][ni][2]), "+f"(acc[mi][ni][3])
                    : "r"(a[mi][0]), "r"(a[mi][1]),
                      "r"(a[mi][2]), "r"(a[mi][3]),
                      "r"(b[ni][0]), "r"(b[ni][1]));
            }
    }

    // ---- Epilogue: add bias, store float2 pairs (same proven layout).
    #pragma unroll
    for (int mi = 0; mi < 2; ++mi) {
        int row0 = e0 + warp_m * 32 + mi * 16 + lr;
        int row1 = row0 + 8;
        #pragma unroll
        for (int ni = 0; ni < 8; ++ni) {
            int col = warp_n * 64 + ni * 8 + 2 * lc;
            float2 bb = *(const float2*)(bias + col);
            if (row0 < M) {
                float2 o;
                o.x = acc[mi][ni][0] + bb.x;
                o.y = acc[mi][ni][1] + bb.y;
                *(float2*)(out + (size_t)row0 * NOUT + col) = o;
            }
            if (row1 < M) {
                float2 o;
                o.x = acc[mi][ni][2] + bb.x;
                o.y = acc[mi][ni][3] + bb.y;
                *(float2*)(out + (size_t)row1 * NOUT + col) = o;
            }
        }
    }
}

} // namespace

extern "C" void kernel_launch(void* const* d_in, const int* in_sizes, int n_in,
                              void* d_out, int out_size)
{
    const float* V   = (const float*)d_in[0];
    const float* E   = (const float*)d_in[1];
    const int*   EI  = (const int*)d_in[2];   // int32 (JAX canonicalized), row 0 = src
    const float* W   = (const float*)d_in[3];
    const float* b   = (const float*)d_in[4];
    float*       out = (float*)d_out;

    const int M = in_sizes[1] / BOND;
    const int grid = (M + BM - 1) / BM;

    cudaFuncSetAttribute(bond_msg_kernel,
                         cudaFuncAttributeMaxDynamicSharedMemorySize, SMEM_BYTES);
    bond_msg_kernel<<<grid, NTHREADS, SMEM_BYTES>>>(V, E, EI, W, b, out, M);
}

// round 6
// speedup vs baseline: 1.9608x; 1.4739x over previous
#include <cuda_runtime.h>
#include <cuda_fp16.h>
#include <cstdint>

namespace {

constexpr int ATOM = 128;
constexpr int BOND = 64;
constexpr int KTOT = 192;    // 48 float4 per row
constexpr int NOUT = 256;
constexpr int BM   = 128;    // edges per tile
constexpr int NTHREADS = 512;
constexpr int STRIDE = 100;  // padded row stride in words -> conflict-free frag LDS

// smem layout (4B words): B first, then two A buffers
constexpr int SM_B_W  = 0;                        // 256 x 100
constexpr int SM_A0_W = NOUT * STRIDE;            // 128 x 100
constexpr int SM_A1_W = SM_A0_W + BM * STRIDE;
constexpr int SMEM_BYTES = (SM_A1_W + BM * STRIDE) * 4;   // 204800

__device__ __forceinline__ uint32_t h2(float lo, float hi) {
    __half2 h = __floats2half2_rn(lo, hi);
    return *(uint32_t*)&h;
}

__global__ void __launch_bounds__(NTHREADS, 1)
bond_msg_kernel(const float* __restrict__ V,
                const float* __restrict__ E,
                const int* __restrict__ src0,      // edge_index row 0 (int32)
                const float* __restrict__ W,       // [NOUT, KTOT]
                const float* __restrict__ bias,    // [NOUT]
                float* __restrict__ out,           // [M, NOUT]
                int M, int ntiles)
{
    extern __shared__ uint32_t smem[];
    uint32_t* Bs = smem + SM_B_W;
    uint32_t* Abuf[2] = { smem + SM_A0_W, smem + SM_A1_W };

    const int tid  = threadIdx.x;
    const int lane = tid & 31;
    const int wid  = tid >> 5;
    const int warp_m = wid >> 2;   // 0..3 (32 rows each)
    const int warp_n = wid & 3;    // 0..3 (64 cols each)
    const int lr = lane >> 2;
    const int lc = lane & 3;
    const int G  = gridDim.x;

    // ---- Fill W once per CTA (persistent): 12288 float4, 24 per thread.
    #pragma unroll
    for (int i = 0; i < 24; ++i) {
        int idx = tid + i * NTHREADS;
        int n  = idx / 48;
        int c4 = idx % 48;
        float4 v = *(const float4*)(W + (size_t)n * KTOT + c4 * 4);
        uint32_t* d = Bs + n * STRIDE + c4 * 2;
        d[0] = h2(v.x, v.y);
        d[1] = h2(v.z, v.w);
    }

    // ---- Prologue: fill A[0] for the first tile.
    int t0 = blockIdx.x;
    if (t0 < ntiles) {
        int e0 = t0 * BM;
        #pragma unroll
        for (int i = 0; i < 12; ++i) {
            int idx = tid + i * NTHREADS;
            int r  = idx / 48;
            int c4 = idx % 48;
            int e  = e0 + r; if (e >= M) e = M - 1;
            const float* p = (c4 < 32)
                ? (V + (size_t)__ldg(src0 + e) * ATOM + c4 * 4)
                : (E + (size_t)e * BOND + (c4 - 32) * 4);
            float4 v = *(const float4*)p;
            uint32_t* d = Abuf[0] + r * STRIDE + c4 * 2;
            d[0] = h2(v.x, v.y);
            d[1] = h2(v.z, v.w);
        }
    }
    __syncthreads();

    int cur = 0;
    for (int t = t0; t < ntiles; t += G) {
        const int e0  = t * BM;
        const int tn  = t + G;
        const bool hn = (tn < ntiles);
        const int e0n = tn * BM;
        const uint32_t* Ac = Abuf[cur];
        uint32_t* An = Abuf[cur ^ 1];

        float acc[2][8][4];
        #pragma unroll
        for (int mi = 0; mi < 2; ++mi)
            #pragma unroll
            for (int ni = 0; ni < 8; ++ni)
                #pragma unroll
                for (int c = 0; c < 4; ++c)
                    acc[mi][ni][c] = 0.f;

        // 3 pipeline stages: prefetch batch b (4 float4) -> 4 MMA k-steps -> STS batch b
        #pragma unroll
        for (int b = 0; b < 3; ++b) {
            float4 g[4];
            if (hn) {
                #pragma unroll
                for (int i = 0; i < 4; ++i) {
                    int idx = tid + (b * 4 + i) * NTHREADS;
                    int r  = idx / 48;
                    int c4 = idx % 48;
                    int e  = e0n + r; if (e >= M) e = M - 1;
                    const float* p = (c4 < 32)
                        ? (V + (size_t)__ldg(src0 + e) * ATOM + c4 * 4)
                        : (E + (size_t)e * BOND + (c4 - 32) * 4);
                    g[i] = *(const float4*)p;
                }
            }

            #pragma unroll
            for (int kk = b * 4; kk < b * 4 + 4; ++kk) {
                const int kb = kk * 8;
                uint32_t a[2][4], bf[8][2];
                #pragma unroll
                for (int mi = 0; mi < 2; ++mi) {
                    int r = warp_m * 32 + mi * 16 + lr;
                    const uint32_t* ap = Ac + r * STRIDE + kb;
                    a[mi][0] = ap[lc];
                    a[mi][1] = ap[8 * STRIDE + lc];
                    a[mi][2] = ap[lc + 4];
                    a[mi][3] = ap[8 * STRIDE + lc + 4];
                }
                #pragma unroll
                for (int ni = 0; ni < 8; ++ni) {
                    int n = warp_n * 64 + ni * 8 + lr;
                    const uint32_t* bp = Bs + n * STRIDE + kb;
                    bf[ni][0] = bp[lc];
                    bf[ni][1] = bp[lc + 4];
                }
                #pragma unroll
                for (int mi = 0; mi < 2; ++mi)
                    #pragma unroll
                    for (int ni = 0; ni < 8; ++ni) {
                        asm volatile(
                            "mma.sync.aligned.m16n8k16.row.col.f32.f16.f16.f32 "
                            "{%0,%1,%2,%3}, {%4,%5,%6,%7}, {%8,%9}, {%0,%1,%2,%3};\n"
                            : "+f"(acc[mi][ni][0]), "+f"(acc[mi][ni][1]),
                              "+f"(acc[mi][ni][2]), "+f"(acc[mi][ni][3])
                            : "r"(a[mi][0]), "r"(a[mi][1]),
                              "r"(a[mi][2]), "r"(a[mi][3]),
                              "r"(bf[ni][0]), "r"(bf[ni][1]));
                    }
            }

            if (hn) {
                #pragma unroll
                for (int i = 0; i < 4; ++i) {
                    int idx = tid + (b * 4 + i) * NTHREADS;
                    int r  = idx / 48;
                    int c4 = idx % 48;
                    uint32_t* d = An + r * STRIDE + c4 * 2;
                    d[0] = h2(g[i].x, g[i].y);
                    d[1] = h2(g[i].z, g[i].w);
                }
            }
        }

        // ---- Epilogue: add bias, store float2 pairs (proven layout).
        #pragma unroll
        for (int mi = 0; mi < 2; ++mi) {
            int row0 = e0 + warp_m * 32 + mi * 16 + lr;
            int row1 = row0 + 8;
            #pragma unroll
            for (int ni = 0; ni < 8; ++ni) {
                int col = warp_n * 64 + ni * 8 + 2 * lc;
                float2 bb = *(const float2*)(bias + col);
                if (row0 < M) {
                    float2 o;
                    o.x = acc[mi][ni][0] + bb.x;
                    o.y = acc[mi][ni][1] + bb.y;
                    *(float2*)(out + (size_t)row0 * NOUT + col) = o;
                }
                if (row1 < M) {
                    float2 o;
                    o.x = acc[mi][ni][2] + bb.x;
                    o.y = acc[mi][ni][3] + bb.y;
                    *(float2*)(out + (size_t)row1 * NOUT + col) = o;
                }
            }
        }

        __syncthreads();     // A[cur^1] fully written; acc consumed
        cur ^= 1;
    }
}

} // namespace

extern "C" void kernel_launch(void* const* d_in, const int* in_sizes, int n_in,
                              void* d_out, int out_size)
{
    const float* V   = (const float*)d_in[0];
    const float* E   = (const float*)d_in[1];
    const int*   EI  = (const int*)d_in[2];   // int32 (JAX canonicalized), row 0 = src
    const float* W   = (const float*)d_in[3];
    const float* b   = (const float*)d_in[4];
    float*       out = (float*)d_out;

    const int M = in_sizes[1] / BOND;
    const int ntiles = (M + BM - 1) / BM;

    int sms = 148;
    cudaDeviceGetAttribute(&sms, cudaDevAttrMultiProcessorCount, 0);
    int grid = sms < ntiles ? sms : ntiles;

    cudaFuncSetAttribute(bond_msg_kernel,
                         cudaFuncAttributeMaxDynamicSharedMemorySize, SMEM_BYTES);
    bond_msg_kernel<<<grid, NTHREADS, SMEM_BYTES>>>(V, E, EI, W, b, out, M, ntiles);
}